// round 1
// baseline (speedup 1.0000x reference)
#include <cuda_runtime.h>
#include <cuda_bf16.h>
#include <cstdint>

// pooled[i][j] = 1.0 if any k in [j-25, j+25] (clamped to [0,M)) has |in[i]-w[k]| < 0.1, else 0.0
// N = 1024 rows, M = 262144 cols, output 1 GiB fp32 -> HBM-store-bound.
//
// Strategy: bit-pack the mask (1 bit per k), sliding-OR of width 51 via
// log-step 64-bit dilation, emit 32 outputs per thread as 8x float4 stores.
// Each block caches an 8192-weight chunk (+/-32 halo) in smem and serves
// ROWS_PER_BLOCK rows to amortize weight traffic.

#define THREADS 256
#define WPT 32                       // outputs (and mask bits) per thread
#define CHUNK (THREADS * WPT)        // 8192 weights per block chunk
#define HALO 32                      // >= 25 (pool radius)
#define ROWS_PER_BLOCK 16
#define THRESH 0.1f
#define OOR_VAL 3.0e38f              // out-of-range weight sentinel: |in - OOR| >= 0.1 always

__global__ __launch_bounds__(THREADS)
void cll_pool_kernel(const float* __restrict__ in_feat,
                     const float* __restrict__ weights,
                     float* __restrict__ out,
                     int N, int M)
{
    __shared__ float wsm[CHUNK + 2 * HALO];
    __shared__ unsigned mbuf[2][THREADS + 2];   // double-buffered neighbor mask words

    const int t = threadIdx.x;
    const int chunkbase = blockIdx.x * CHUNK;

    // Load weight chunk with halo; out-of-range -> sentinel (mask bit 0 == -inf pad)
    for (int idx = t; idx < CHUNK + 2 * HALO; idx += THREADS) {
        int g = chunkbase - HALO + idx;
        wsm[idx] = (g >= 0 && g < M) ? weights[g] : OOR_VAL;
    }
    __syncthreads();

    const int row0 = blockIdx.y * ROWS_PER_BLOCK;

    #pragma unroll 1
    for (int r = 0; r < ROWS_PER_BLOCK; ++r) {
        int i = row0 + r;
        if (i >= N) i = N - 1;            // tail blocks rewrite last row (same values; harmless)
        const float vi = in_feat[i];
        const int buf = r & 1;

        // Build this thread's 32-bit mask word: bit b = |vi - w[base+b]| < 0.1
        {
            const float* wp = wsm + HALO + t * WPT;
            unsigned m = 0;
            #pragma unroll
            for (int b = 0; b < 32; ++b)
                m |= (fabsf(vi - wp[b]) < THRESH ? 1u : 0u) << b;
            mbuf[buf][t + 1] = m;
        }
        // Halo words (left of chunk / right of chunk), built by two different warps
        if (t == 0) {
            unsigned h = 0;
            #pragma unroll
            for (int b = 0; b < 32; ++b)
                h |= (fabsf(vi - wsm[b]) < THRESH ? 1u : 0u) << b;
            mbuf[buf][0] = h;
        }
        if (t == THREADS - 1) {
            const float* wph = wsm + HALO + CHUNK;
            unsigned h = 0;
            #pragma unroll
            for (int b = 0; b < 32; ++b)
                h |= (fabsf(vi - wph[b]) < THRESH ? 1u : 0u) << b;
            mbuf[buf][THREADS + 1] = h;
        }
        __syncthreads();

        const unsigned wm1 = mbuf[buf][t];       // bits [base-32, base)
        const unsigned w0  = mbuf[buf][t + 1];   // bits [base, base+32)
        const unsigned wp1 = mbuf[buf][t + 2];   // bits [base+32, base+64)

        // lo: bits [base-32, base+32); hi: bits [base, base+64)
        unsigned long long lo = (unsigned long long)wm1 | ((unsigned long long)w0 << 32);
        unsigned long long hi = (unsigned long long)w0  | ((unsigned long long)wp1 << 32);

        // Right-dilate hi by 26: bit j -> OR of hi bits j..j+25  (covers d = 0..+25)
        hi |= hi >> 1;  hi |= hi >> 2;  hi |= hi >> 4;  hi |= hi >> 8;  hi |= hi >> 10;
        // Left-dilate lo by 26: bit t -> OR of lo bits t-25..t   (covers d = -25..0)
        lo |= lo << 1;  lo |= lo << 2;  lo |= lo << 4;  lo |= lo << 8;  lo |= lo << 10;

        const unsigned p = (unsigned)hi | (unsigned)(lo >> 32);

        // Emit 32 outputs as 8x float4
        const int col = chunkbase + t * WPT;
        float* orow = out + (size_t)i * (size_t)M + col;
        if (col + WPT <= M) {
            float4* o4 = reinterpret_cast<float4*>(orow);
            #pragma unroll
            for (int g = 0; g < 8; ++g) {
                float4 v;
                v.x = (p >> (4 * g + 0)) & 1u ? 1.0f : 0.0f;
                v.y = (p >> (4 * g + 1)) & 1u ? 1.0f : 0.0f;
                v.z = (p >> (4 * g + 2)) & 1u ? 1.0f : 0.0f;
                v.w = (p >> (4 * g + 3)) & 1u ? 1.0f : 0.0f;
                o4[g] = v;
            }
        } else {
            for (int b = 0; b < WPT && col + b < M; ++b)
                orow[b] = (p >> b) & 1u ? 1.0f : 0.0f;
        }
        // No trailing barrier needed: next row writes the other mask buffer,
        // and the per-row barrier orders buffer reuse two rows apart.
    }
}

extern "C" void kernel_launch(void* const* d_in, const int* in_sizes, int n_in,
                              void* d_out, int out_size)
{
    const float* in_feat = (const float*)d_in[0];   // [2, 512] -> N = 1024
    const float* weights = (const float*)d_in[1];   // [512, 512] -> M = 262144
    float* out = (float*)d_out;

    const int N = in_sizes[0];
    const int M = in_sizes[1];

    dim3 grid((M + CHUNK - 1) / CHUNK, (N + ROWS_PER_BLOCK - 1) / ROWS_PER_BLOCK);
    cll_pool_kernel<<<grid, THREADS>>>(in_feat, weights, out, N, M);
}

// round 2
// speedup vs baseline: 1.3823x; 1.3823x over previous
#include <cuda_runtime.h>
#include <cuda_bf16.h>
#include <cstdint>

// pooled[i][j] = 1.0 if any k in [j-25, j+25] (in-range) has |in[i]-w[k]| < 0.1
// N=1024, M=262144 -> 1 GiB fp32 output, HBM-store-bound target.
//
// R2: weights live in REGISTERS (8 x LDG.128 per thread, reused over 16 rows).
// Round 1 was L1-bound (79.5%) from 32-way LDS bank conflicts on the smem
// weight reads; those are gone. Per-row smem traffic is only the conflict-free
// mask-word neighbor exchange + a 64-float halo buffer touched by 2 threads.

#define THREADS 256
#define WPT 32                       // outputs / mask bits per thread
#define CHUNK (THREADS * WPT)        // 8192 weights per block
#define ROWS_PER_BLOCK 16
#define THRESH 0.1f
#define OOR_VAL 3.0e38f              // sentinel: |in - OOR| >= 0.1 always (== -inf pad)

__global__ __launch_bounds__(THREADS)
void cll_pool_kernel(const float* __restrict__ in_feat,
                     const float* __restrict__ weights,
                     float* __restrict__ out,
                     int N, int M)
{
    __shared__ float hsm[64];                 // [0:32) left halo, [32:64) right halo
    __shared__ unsigned mbuf[2][THREADS + 2]; // double-buffered mask-word exchange

    const int t = threadIdx.x;
    const int chunkbase = blockIdx.x * CHUNK;

    // ---- one-time loads ----
    // This thread's 32 weights -> registers (coalesced 16B loads)
    float4 w4[8];
    {
        const int g0 = chunkbase + t * WPT;
        if (g0 + WPT <= M) {
            const float4* wp = reinterpret_cast<const float4*>(weights + g0);
            #pragma unroll
            for (int g = 0; g < 8; ++g) w4[g] = wp[g];
        } else {
            #pragma unroll
            for (int g = 0; g < 8; ++g) {
                float tmp[4];
                #pragma unroll
                for (int c = 0; c < 4; ++c) {
                    int gg = g0 + g * 4 + c;
                    tmp[c] = (gg < M) ? weights[gg] : OOR_VAL;
                }
                w4[g] = make_float4(tmp[0], tmp[1], tmp[2], tmp[3]);
            }
        }
    }
    // Halo weights (32 left of chunk, 32 right of chunk) -> smem
    if (t < 64) {
        int g = (t < 32) ? (chunkbase - 32 + t) : (chunkbase + CHUNK + (t - 32));
        hsm[t] = (g >= 0 && g < M) ? weights[g] : OOR_VAL;
    }
    __syncthreads();

    const int row0 = blockIdx.y * ROWS_PER_BLOCK;

    #pragma unroll 1
    for (int r = 0; r < ROWS_PER_BLOCK; ++r) {
        int i = row0 + r;
        if (i >= N) i = N - 1;                // tail safety (grid divides exactly here)
        const float vi = __ldg(&in_feat[i]);  // broadcast, L1-resident
        const int buf = r & 1;

        // ---- build this thread's 32-bit mask word from registers ----
        unsigned m = 0;
        #pragma unroll
        for (int g = 0; g < 8; ++g) {
            m |= (fabsf(vi - w4[g].x) < THRESH ? 1u : 0u) << (4 * g + 0);
            m |= (fabsf(vi - w4[g].y) < THRESH ? 1u : 0u) << (4 * g + 1);
            m |= (fabsf(vi - w4[g].z) < THRESH ? 1u : 0u) << (4 * g + 2);
            m |= (fabsf(vi - w4[g].w) < THRESH ? 1u : 0u) << (4 * g + 3);
        }
        mbuf[buf][t + 1] = m;

        // halo mask words (2 threads; smem reads are single-thread -> no conflicts)
        if (t == 0) {
            unsigned h = 0;
            #pragma unroll
            for (int b = 0; b < 32; ++b)
                h |= (fabsf(vi - hsm[b]) < THRESH ? 1u : 0u) << b;
            mbuf[buf][0] = h;
        }
        if (t == THREADS - 1) {
            unsigned h = 0;
            #pragma unroll
            for (int b = 0; b < 32; ++b)
                h |= (fabsf(vi - hsm[32 + b]) < THRESH ? 1u : 0u) << b;
            mbuf[buf][THREADS + 1] = h;
        }
        __syncthreads();

        const unsigned wm1 = mbuf[buf][t];       // bits [base-32, base)
        const unsigned wp1 = mbuf[buf][t + 2];   // bits [base+32, base+64)

        // lo: bits [base-32, base+32); hi: bits [base, base+64)
        unsigned long long lo = (unsigned long long)wm1 | ((unsigned long long)m << 32);
        unsigned long long hi = (unsigned long long)m   | ((unsigned long long)wp1 << 32);

        // right-dilate hi by 25 (d = 0..+25), left-dilate lo by 25 (d = -25..0)
        hi |= hi >> 1;  hi |= hi >> 2;  hi |= hi >> 4;  hi |= hi >> 8;  hi |= hi >> 10;
        lo |= lo << 1;  lo |= lo << 2;  lo |= lo << 4;  lo |= lo << 8;  lo |= lo << 10;

        const unsigned p = (unsigned)hi | (unsigned)(lo >> 32);

        // ---- emit 32 outputs as 8 x STG.128 ----
        const int col = chunkbase + t * WPT;
        float* orow = out + (size_t)i * (size_t)M + col;
        if (col + WPT <= M) {
            float4* o4 = reinterpret_cast<float4*>(orow);
            #pragma unroll
            for (int g = 0; g < 8; ++g) {
                float4 v;
                v.x = __uint_as_float(((p >> (4 * g + 0)) & 1u) * 0x3F800000u);
                v.y = __uint_as_float(((p >> (4 * g + 1)) & 1u) * 0x3F800000u);
                v.z = __uint_as_float(((p >> (4 * g + 2)) & 1u) * 0x3F800000u);
                v.w = __uint_as_float(((p >> (4 * g + 3)) & 1u) * 0x3F800000u);
                o4[g] = v;
            }
        } else {
            for (int b = 0; b < WPT && col + b < M; ++b)
                orow[b] = __uint_as_float(((p >> b) & 1u) * 0x3F800000u);
        }
        // next row uses the other mbuf buffer; the per-row barrier two rows
        // apart orders buffer reuse.
    }
}

extern "C" void kernel_launch(void* const* d_in, const int* in_sizes, int n_in,
                              void* d_out, int out_size)
{
    const float* in_feat = (const float*)d_in[0];   // 1024 elements
    const float* weights = (const float*)d_in[1];   // 262144 elements
    float* out = (float*)d_out;

    const int N = in_sizes[0];
    const int M = in_sizes[1];

    dim3 grid((M + CHUNK - 1) / CHUNK, (N + ROWS_PER_BLOCK - 1) / ROWS_PER_BLOCK);
    cll_pool_kernel<<<grid, THREADS>>>(in_feat, weights, out, N, M);
}

// round 3
// speedup vs baseline: 3.5042x; 2.5350x over previous
#include <cuda_runtime.h>
#include <cuda_bf16.h>
#include <cstdint>

// pooled[i][j] = 1.0 if any k in [j-25, j+25] (in-range) has |in[i]-w[k]| < 0.1
// N=1024, M=262144 -> 1 GiB fp32 output; target is the HBM write roofline.
//
// R3: coalesced stores. R2 had each thread writing its own 128B range, so a
// warp STG.128 touched 32 distinct lines (8x wavefront inflation; L1=59%,
// L2=68%, DRAM only 33%). Now the pooled bit-words are redistributed across
// the warp with shuffles so each warp store writes 512 contiguous bytes.

#define THREADS 256
#define WPT 32                       // pooled bits per thread
#define CHUNK (THREADS * WPT)        // 8192 weights/columns per block
#define ROWS_PER_BLOCK 16
#define THRESH 0.1f
#define OOR_VAL 3.0e38f              // sentinel == -inf pad (never within 0.1)

__global__ __launch_bounds__(THREADS)
void cll_pool_kernel(const float* __restrict__ in_feat,
                     const float* __restrict__ weights,
                     float* __restrict__ out,
                     int N, int M)
{
    __shared__ float hsm[64];                 // [0:32) left halo, [32:64) right halo
    __shared__ unsigned mbuf[2][THREADS + 2]; // double-buffered mask-word exchange

    const int t = threadIdx.x;
    const int lane = t & 31;
    const int warp = t >> 5;
    const int chunkbase = blockIdx.x * CHUNK;

    // ---- one-time loads ----
    float4 w4[8];                             // this thread's 32 weights in registers
    {
        const int g0 = chunkbase + t * WPT;
        if (g0 + WPT <= M) {
            const float4* wp = reinterpret_cast<const float4*>(weights + g0);
            #pragma unroll
            for (int g = 0; g < 8; ++g) w4[g] = wp[g];
        } else {
            #pragma unroll
            for (int g = 0; g < 8; ++g) {
                float tmp[4];
                #pragma unroll
                for (int c = 0; c < 4; ++c) {
                    int gg = g0 + g * 4 + c;
                    tmp[c] = (gg < M) ? weights[gg] : OOR_VAL;
                }
                w4[g] = make_float4(tmp[0], tmp[1], tmp[2], tmp[3]);
            }
        }
    }
    if (t < 64) {
        int g = (t < 32) ? (chunkbase - 32 + t) : (chunkbase + CHUNK + (t - 32));
        hsm[t] = (g >= 0 && g < M) ? weights[g] : OOR_VAL;
    }
    __syncthreads();

    const int row0 = blockIdx.y * ROWS_PER_BLOCK;

    #pragma unroll 1
    for (int r = 0; r < ROWS_PER_BLOCK; ++r) {
        int i = row0 + r;
        if (i >= N) i = N - 1;
        const float vi = __ldg(&in_feat[i]);
        const int buf = r & 1;

        // ---- mask word from registers ----
        unsigned m = 0;
        #pragma unroll
        for (int g = 0; g < 8; ++g) {
            m |= (fabsf(vi - w4[g].x) < THRESH ? 1u : 0u) << (4 * g + 0);
            m |= (fabsf(vi - w4[g].y) < THRESH ? 1u : 0u) << (4 * g + 1);
            m |= (fabsf(vi - w4[g].z) < THRESH ? 1u : 0u) << (4 * g + 2);
            m |= (fabsf(vi - w4[g].w) < THRESH ? 1u : 0u) << (4 * g + 3);
        }
        mbuf[buf][t + 1] = m;

        if (t == 0) {
            unsigned h = 0;
            #pragma unroll
            for (int b = 0; b < 32; ++b)
                h |= (fabsf(vi - hsm[b]) < THRESH ? 1u : 0u) << b;
            mbuf[buf][0] = h;
        }
        if (t == THREADS - 1) {
            unsigned h = 0;
            #pragma unroll
            for (int b = 0; b < 32; ++b)
                h |= (fabsf(vi - hsm[32 + b]) < THRESH ? 1u : 0u) << b;
            mbuf[buf][THREADS + 1] = h;
        }
        __syncthreads();

        const unsigned wm1 = mbuf[buf][t];       // bits [base-32, base)
        const unsigned wp1 = mbuf[buf][t + 2];   // bits [base+32, base+64)

        unsigned long long lo = (unsigned long long)wm1 | ((unsigned long long)m << 32);
        unsigned long long hi = (unsigned long long)m   | ((unsigned long long)wp1 << 32);

        // width-51 sliding OR via log-step dilation (radius 25 each side)
        hi |= hi >> 1;  hi |= hi >> 2;  hi |= hi >> 4;  hi |= hi >> 8;  hi |= hi >> 10;
        lo |= lo << 1;  lo |= lo << 2;  lo |= lo << 4;  lo |= lo << 8;  lo |= lo << 10;

        const unsigned p = (unsigned)hi | (unsigned)(lo >> 32);   // pooled bits for cols [t*32, t*32+32)

        // ---- coalesced emit: warp covers 1024 contiguous columns ----
        // store step s: lane writes float4 at warpcol + s*128 + lane*4.
        // needed bits live in lane (s*4 + lane/8)'s p, at offset (lane%8)*4.
        float* wout = out + (size_t)i * (size_t)M + chunkbase + warp * 1024;
        const int shamt = (lane & 7) * 4;
        const int srcbase = lane >> 3;
        #pragma unroll
        for (int s = 0; s < 8; ++s) {
            unsigned src = __shfl_sync(0xFFFFFFFFu, p, s * 4 + srcbase);
            unsigned bits = src >> shamt;
            float4 v;
            v.x = __uint_as_float((bits        & 1u) * 0x3F800000u);
            v.y = __uint_as_float(((bits >> 1) & 1u) * 0x3F800000u);
            v.z = __uint_as_float(((bits >> 2) & 1u) * 0x3F800000u);
            v.w = __uint_as_float(((bits >> 3) & 1u) * 0x3F800000u);
            reinterpret_cast<float4*>(wout + s * 128)[lane] = v;
        }
    }
}

extern "C" void kernel_launch(void* const* d_in, const int* in_sizes, int n_in,
                              void* d_out, int out_size)
{
    const float* in_feat = (const float*)d_in[0];   // 1024 elements
    const float* weights = (const float*)d_in[1];   // 262144 elements
    float* out = (float*)d_out;

    const int N = in_sizes[0];
    const int M = in_sizes[1];

    dim3 grid((M + CHUNK - 1) / CHUNK, (N + ROWS_PER_BLOCK - 1) / ROWS_PER_BLOCK);
    cll_pool_kernel<<<grid, THREADS>>>(in_feat, weights, out, N, M);
}

// round 4
// speedup vs baseline: 3.6292x; 1.0357x over previous
#include <cuda_runtime.h>
#include <cuda_bf16.h>
#include <cstdint>

// pooled[i][j] = 1.0 if any k in [j-25, j+25] (in-range) has |in[i]-w[k]| < 0.1
// N=1024, M=262144 -> 1 GiB fp32 output; HBM write roofline target.
//
// R4 vs R3 (160us, DRAM 82%):
//  - halo mask words via warp-parallel __ballot_sync (kills the 2-thread
//    serial halo section that stalled every row at the barrier)
//  - software-pipelined rows: next row's mask build overlaps current row's
//    dilate+store, hiding barrier skew
//  - ROWS_PER_BLOCK 16->8: finer grid for tail balance (weights are
//    L2-resident, so re-reads are DRAM-free)
//  - streaming stores (__stcs)

#define THREADS 256
#define NWARP (THREADS / 32)
#define WPT 32                       // pooled bits per thread
#define CHUNK (THREADS * WPT)        // 8192 columns per block
#define ROWS_PER_BLOCK 8
#define THRESH 0.1f
#define OOR_VAL 3.0e38f              // sentinel == -inf pad (never within 0.1)

__device__ __forceinline__ unsigned mask32(float vi, const float4* w4)
{
    unsigned m = 0;
    #pragma unroll
    for (int g = 0; g < 8; ++g) {
        m |= (fabsf(vi - w4[g].x) < THRESH ? 1u : 0u) << (4 * g + 0);
        m |= (fabsf(vi - w4[g].y) < THRESH ? 1u : 0u) << (4 * g + 1);
        m |= (fabsf(vi - w4[g].z) < THRESH ? 1u : 0u) << (4 * g + 2);
        m |= (fabsf(vi - w4[g].w) < THRESH ? 1u : 0u) << (4 * g + 3);
    }
    return m;
}

__global__ __launch_bounds__(THREADS)
void cll_pool_kernel(const float* __restrict__ in_feat,
                     const float* __restrict__ weights,
                     float* __restrict__ out,
                     int N, int M)
{
    __shared__ unsigned mbuf[2][THREADS + 2];   // double-buffered mask-word exchange

    const int t = threadIdx.x;
    const int lane = t & 31;
    const int warp = t >> 5;
    const int chunkbase = blockIdx.x * CHUNK;

    // ---- one-time loads ----
    float4 w4[8];                               // this thread's 32 weights
    {
        const int g0 = chunkbase + t * WPT;
        if (g0 + WPT <= M) {
            const float4* wp = reinterpret_cast<const float4*>(weights + g0);
            #pragma unroll
            for (int g = 0; g < 8; ++g) w4[g] = wp[g];
        } else {
            #pragma unroll
            for (int g = 0; g < 8; ++g) {
                float tmp[4];
                #pragma unroll
                for (int c = 0; c < 4; ++c) {
                    int gg = g0 + g * 4 + c;
                    tmp[c] = (gg < M) ? weights[gg] : OOR_VAL;
                }
                w4[g] = make_float4(tmp[0], tmp[1], tmp[2], tmp[3]);
            }
        }
    }
    // halo weight for ballot: warp 0 -> left halo, last warp -> right halo
    float hw;
    {
        int hg = (warp == 0) ? (chunkbase - 32 + lane)
                             : (chunkbase + CHUNK + lane);
        hw = (hg >= 0 && hg < M) ? __ldg(weights + hg) : OOR_VAL;
    }

    const int row0 = blockIdx.y * ROWS_PER_BLOCK;

    // ---- prologue: row 0 mask words into buffer 0 ----
    {
        int i0 = (row0 < N) ? row0 : N - 1;
        const float vi = __ldg(&in_feat[i0]);
        mbuf[0][t + 1] = mask32(vi, w4);
        unsigned hword = __ballot_sync(0xFFFFFFFFu, fabsf(vi - hw) < THRESH);
        if (warp == 0 && lane == 0)         mbuf[0][0] = hword;
        if (warp == NWARP - 1 && lane == 0) mbuf[0][THREADS + 1] = hword;
    }

    unsigned m_cur;   // set from mbuf read each iteration via own write: keep in reg
    // keep own mask in a register across the pipeline
    // (recompute path: we wrote it above; re-read is free from reg if we stash it)
    // simplest: recompute stash
    {
        int i0 = (row0 < N) ? row0 : N - 1;
        m_cur = mask32(__ldg(&in_feat[i0]), w4);   // CSE'd with prologue by compiler
    }

    #pragma unroll 1
    for (int r = 0; r < ROWS_PER_BLOCK; ++r) {
        __syncthreads();
        const int buf = r & 1;
        int i = row0 + r;
        if (i >= N) i = N - 1;

        const unsigned wm1 = mbuf[buf][t];          // bits [base-32, base)
        const unsigned wp1 = mbuf[buf][t + 2];      // bits [base+32, base+64)

        // ---- pipeline: build next row's words into the other buffer ----
        unsigned m_next = 0;
        if (r + 1 < ROWS_PER_BLOCK) {
            int in2 = row0 + r + 1;
            if (in2 >= N) in2 = N - 1;
            const float vn = __ldg(&in_feat[in2]);
            m_next = mask32(vn, w4);
            mbuf[buf ^ 1][t + 1] = m_next;
            unsigned hword = __ballot_sync(0xFFFFFFFFu, fabsf(vn - hw) < THRESH);
            if (warp == 0 && lane == 0)         mbuf[buf ^ 1][0] = hword;
            if (warp == NWARP - 1 && lane == 0) mbuf[buf ^ 1][THREADS + 1] = hword;
        }

        // ---- width-51 sliding OR (radius 25) via log-step dilation ----
        unsigned long long lo = (unsigned long long)wm1   | ((unsigned long long)m_cur << 32);
        unsigned long long hi = (unsigned long long)m_cur | ((unsigned long long)wp1 << 32);
        hi |= hi >> 1;  hi |= hi >> 2;  hi |= hi >> 4;  hi |= hi >> 8;  hi |= hi >> 10;
        lo |= lo << 1;  lo |= lo << 2;  lo |= lo << 4;  lo |= lo << 8;  lo |= lo << 10;
        const unsigned p = (unsigned)hi | (unsigned)(lo >> 32);

        // ---- coalesced emit: warp covers 1024 contiguous columns ----
        float* wout = out + (size_t)i * (size_t)M + chunkbase + warp * 1024;
        const int shamt = (lane & 7) * 4;
        const int srcbase = lane >> 3;
        #pragma unroll
        for (int s = 0; s < 8; ++s) {
            unsigned src = __shfl_sync(0xFFFFFFFFu, p, s * 4 + srcbase);
            unsigned bits = src >> shamt;
            float4 v;
            v.x = __uint_as_float((bits        & 1u) * 0x3F800000u);
            v.y = __uint_as_float(((bits >> 1) & 1u) * 0x3F800000u);
            v.z = __uint_as_float(((bits >> 2) & 1u) * 0x3F800000u);
            v.w = __uint_as_float(((bits >> 3) & 1u) * 0x3F800000u);
            __stcs(reinterpret_cast<float4*>(wout + s * 128) + lane, v);
        }

        m_cur = m_next;
    }
}

extern "C" void kernel_launch(void* const* d_in, const int* in_sizes, int n_in,
                              void* d_out, int out_size)
{
    const float* in_feat = (const float*)d_in[0];   // 1024 elements
    const float* weights = (const float*)d_in[1];   // 262144 elements
    float* out = (float*)d_out;

    const int N = in_sizes[0];
    const int M = in_sizes[1];

    dim3 grid((M + CHUNK - 1) / CHUNK, (N + ROWS_PER_BLOCK - 1) / ROWS_PER_BLOCK);
    cll_pool_kernel<<<grid, THREADS>>>(in_feat, weights, out, N, M);
}

// round 5
// speedup vs baseline: 3.7068x; 1.0214x over previous
#include <cuda_runtime.h>
#include <cuda_bf16.h>
#include <cstdint>

// pooled[i][j] = 1.0 if any k in [j-25, j+25] (in-range) has |in[i]-w[k]| < 0.1
// N=1024, M=262144 -> 1 GiB fp32 output; HBM write roofline (~148us) target.
//
// R5 vs R4 (154us, DRAM 83%, ALU 58%, issue 49%): shrink the instruction
// stream per output.
//  - mask build: packed add.rn.f32x2 / fma.rn.f32x2 (s = d*d - 0.01; sign bit
//    == |d| < 0.1) + funnel-shift sign accumulation -> 2 instrs/bit (was ~3)
//  - bit->float expand: (bits & 2^c) * (0x3F800000 >> c) -> 2 instrs/float
//  - unchanged: row pipeline, ballot halo, shuffle-redistributed coalesced
//    STG.128 streaming stores, ROWS_PER_BLOCK=8

#define THREADS 256
#define NWARP (THREADS / 32)
#define WPT 32                       // pooled bits per thread
#define CHUNK (THREADS * WPT)        // 8192 columns per block
#define ROWS_PER_BLOCK 8
#define THRESH 0.1f
#define OOR_VAL 3.0e38f              // sentinel == -inf pad (never within 0.1)

// mask bit b = (vi - w[b])^2 < 0.01  (== |vi-w[b]| < 0.1 up to a 2.6e-9 boundary band)
// nwp[k] = packed(-w[2k], -w[2k+1]); c2 = packed(-0.01f, -0.01f)
__device__ __forceinline__ unsigned mask32_sq(unsigned long long vv,
                                              const unsigned long long* nwp,
                                              unsigned long long c2)
{
    unsigned m = 0;
    #pragma unroll
    for (int k = 15; k >= 0; --k) {
        unsigned long long d, s;
        asm("add.rn.f32x2 %0, %1, %2;" : "=l"(d) : "l"(vv), "l"(nwp[k]));
        asm("fma.rn.f32x2 %0, %1, %1, %2;" : "=l"(s) : "l"(d), "l"(c2));
        const unsigned lo = (unsigned)s;
        const unsigned hi = (unsigned)(s >> 32);
        m = __funnelshift_l(hi, m, 1);   // (m<<1) | sign(hi) : weight 2k+1
        m = __funnelshift_l(lo, m, 1);   // (m<<1) | sign(lo) : weight 2k
    }
    return m;   // bit b == weight b in range
}

__global__ __launch_bounds__(THREADS)
void cll_pool_kernel(const float* __restrict__ in_feat,
                     const float* __restrict__ weights,
                     float* __restrict__ out,
                     int N, int M)
{
    __shared__ unsigned mbuf[2][THREADS + 2];   // double-buffered mask-word exchange

    const int t = threadIdx.x;
    const int lane = t & 31;
    const int warp = t >> 5;
    const int chunkbase = blockIdx.x * CHUNK;

    // ---- one-time loads: 32 weights -> 16 packed negated pairs ----
    unsigned long long nwp[16];
    {
        const int g0 = chunkbase + t * WPT;
        float wv[32];
        if (g0 + WPT <= M) {
            const float4* wp = reinterpret_cast<const float4*>(weights + g0);
            #pragma unroll
            for (int g = 0; g < 8; ++g) {
                float4 q = wp[g];
                wv[4*g+0] = q.x; wv[4*g+1] = q.y; wv[4*g+2] = q.z; wv[4*g+3] = q.w;
            }
        } else {
            #pragma unroll
            for (int b = 0; b < 32; ++b) {
                int gg = g0 + b;
                wv[b] = (gg < M) ? weights[gg] : OOR_VAL;
            }
        }
        #pragma unroll
        for (int k = 0; k < 16; ++k) {
            unsigned lo = __float_as_uint(-wv[2*k]);
            unsigned hi = __float_as_uint(-wv[2*k+1]);
            nwp[k] = ((unsigned long long)hi << 32) | lo;
        }
    }
    // halo weight for ballot: warp 0 -> left halo, last warp -> right halo
    float hw;
    {
        int hg = (warp == 0) ? (chunkbase - 32 + lane)
                             : (chunkbase + CHUNK + lane);
        hw = (hg >= 0 && hg < M) ? __ldg(weights + hg) : OOR_VAL;
    }

    const unsigned long long c2 =
        ((unsigned long long)__float_as_uint(-0.01f) << 32) | __float_as_uint(-0.01f);

    const int row0 = blockIdx.y * ROWS_PER_BLOCK;

    // ---- prologue: row 0 mask words into buffer 0 ----
    unsigned m_cur;
    {
        int i0 = (row0 < N) ? row0 : N - 1;
        const float vi = __ldg(&in_feat[i0]);
        const unsigned long long vv =
            ((unsigned long long)__float_as_uint(vi) << 32) | __float_as_uint(vi);
        m_cur = mask32_sq(vv, nwp, c2);
        mbuf[0][t + 1] = m_cur;
        unsigned hword = __ballot_sync(0xFFFFFFFFu, fabsf(vi - hw) < THRESH);
        if (warp == 0 && lane == 0)         mbuf[0][0] = hword;
        if (warp == NWARP - 1 && lane == 0) mbuf[0][THREADS + 1] = hword;
    }

    #pragma unroll 1
    for (int r = 0; r < ROWS_PER_BLOCK; ++r) {
        __syncthreads();
        const int buf = r & 1;
        int i = row0 + r;
        if (i >= N) i = N - 1;

        const unsigned wm1 = mbuf[buf][t];          // bits [base-32, base)
        const unsigned wp1 = mbuf[buf][t + 2];      // bits [base+32, base+64)

        // ---- pipeline: build next row's words into the other buffer ----
        unsigned m_next = 0;
        if (r + 1 < ROWS_PER_BLOCK) {
            int in2 = row0 + r + 1;
            if (in2 >= N) in2 = N - 1;
            const float vn = __ldg(&in_feat[in2]);
            const unsigned long long vv =
                ((unsigned long long)__float_as_uint(vn) << 32) | __float_as_uint(vn);
            m_next = mask32_sq(vv, nwp, c2);
            mbuf[buf ^ 1][t + 1] = m_next;
            unsigned hword = __ballot_sync(0xFFFFFFFFu, fabsf(vn - hw) < THRESH);
            if (warp == 0 && lane == 0)         mbuf[buf ^ 1][0] = hword;
            if (warp == NWARP - 1 && lane == 0) mbuf[buf ^ 1][THREADS + 1] = hword;
        }

        // ---- width-51 sliding OR (radius 25) via log-step dilation ----
        unsigned long long lo = (unsigned long long)wm1   | ((unsigned long long)m_cur << 32);
        unsigned long long hi = (unsigned long long)m_cur | ((unsigned long long)wp1 << 32);
        hi |= hi >> 1;  hi |= hi >> 2;  hi |= hi >> 4;  hi |= hi >> 8;  hi |= hi >> 10;
        lo |= lo << 1;  lo |= lo << 2;  lo |= lo << 4;  lo |= lo << 8;  lo |= lo << 10;
        const unsigned p = (unsigned)hi | (unsigned)(lo >> 32);

        // ---- coalesced emit: warp covers 1024 contiguous columns ----
        float* wout = out + (size_t)i * (size_t)M + chunkbase + warp * 1024;
        const int shamt = (lane & 7) * 4;
        const int srcbase = lane >> 3;
        #pragma unroll
        for (int s = 0; s < 8; ++s) {
            unsigned src = __shfl_sync(0xFFFFFFFFu, p, s * 4 + srcbase);
            unsigned bits = src >> shamt;
            float4 v;
            v.x = __uint_as_float((bits & 1u) * 0x3F800000u);
            v.y = __uint_as_float((bits & 2u) * 0x1FC00000u);
            v.z = __uint_as_float((bits & 4u) * 0x0FE00000u);
            v.w = __uint_as_float((bits & 8u) * 0x07F00000u);
            __stcs(reinterpret_cast<float4*>(wout + s * 128) + lane, v);
        }

        m_cur = m_next;
    }
}

extern "C" void kernel_launch(void* const* d_in, const int* in_sizes, int n_in,
                              void* d_out, int out_size)
{
    const float* in_feat = (const float*)d_in[0];   // 1024 elements
    const float* weights = (const float*)d_in[1];   // 262144 elements
    float* out = (float*)d_out;

    const int N = in_sizes[0];
    const int M = in_sizes[1];

    dim3 grid((M + CHUNK - 1) / CHUNK, (N + ROWS_PER_BLOCK - 1) / ROWS_PER_BLOCK);
    cll_pool_kernel<<<grid, THREADS>>>(in_feat, weights, out, N, M);
}

// round 6
// speedup vs baseline: 3.7361x; 1.0079x over previous
#include <cuda_runtime.h>
#include <cuda_bf16.h>
#include <cstdint>

// pooled[i][j] = 1.0 if any k in [j-25, j+25] (in-range) has |in[i]-w[k]| < 0.1
// N=1024, M=262144 -> 1 GiB fp32 output; HBM write roofline target.
//
// R6 vs R5 (151us, DRAM 85.4%, L1 76%): warps fully independent.
//  - each warp owns a contiguous 1024-col segment; neighbor mask words via
//    __shfl_up/down; segment-edge halo words via per-lane halo weights +
//    __ballot_sync. NO smem, NO __syncthreads in the row loop -> no barrier
//    convoy, store pipe continuously fed.
//  - mask build: packed f32x2 FMA sign-bit + funnel shift (2 instrs/bit)
//  - coalesced shuffle-redistributed STG.128 streaming stores

#define THREADS 256
#define WPT 32                       // pooled bits per thread
#define SEG 1024                     // columns per warp
#define CHUNK (THREADS * WPT)        // 8192 columns per block
#define ROWS_PER_BLOCK 8
#define THRESH 0.1f
#define OOR_VAL 3.0e38f              // sentinel == -inf pad (never within 0.1)

// mask bit b = (vi - w[b])^2 < 0.01  (== |vi-w[b]| < 0.1 up to ulp-level boundary band)
__device__ __forceinline__ unsigned mask32_sq(unsigned long long vv,
                                              const unsigned long long* nwp,
                                              unsigned long long c2)
{
    unsigned m = 0;
    #pragma unroll
    for (int k = 15; k >= 0; --k) {
        unsigned long long d, s;
        asm("add.rn.f32x2 %0, %1, %2;" : "=l"(d) : "l"(vv), "l"(nwp[k]));
        asm("fma.rn.f32x2 %0, %1, %1, %2;" : "=l"(s) : "l"(d), "l"(c2));
        const unsigned lo = (unsigned)s;
        const unsigned hi = (unsigned)(s >> 32);
        m = __funnelshift_l(hi, m, 1);   // (m<<1) | sign : weight 2k+1
        m = __funnelshift_l(lo, m, 1);   // (m<<1) | sign : weight 2k
    }
    return m;
}

__global__ __launch_bounds__(THREADS)
void cll_pool_kernel(const float* __restrict__ in_feat,
                     const float* __restrict__ weights,
                     float* __restrict__ out,
                     int N, int M)
{
    const int t = threadIdx.x;
    const int lane = t & 31;
    const int warp = t >> 5;
    const int segbase = blockIdx.x * CHUNK + warp * SEG;   // this warp's first column

    // ---- one-time loads: this thread's 32 weights -> 16 packed negated pairs ----
    unsigned long long nwp[16];
    {
        const int g0 = segbase + lane * WPT;
        float wv[32];
        if (g0 + WPT <= M) {
            const float4* wp = reinterpret_cast<const float4*>(weights + g0);
            #pragma unroll
            for (int g = 0; g < 8; ++g) {
                float4 q = wp[g];
                wv[4*g+0] = q.x; wv[4*g+1] = q.y; wv[4*g+2] = q.z; wv[4*g+3] = q.w;
            }
        } else {
            #pragma unroll
            for (int b = 0; b < 32; ++b) {
                int gg = g0 + b;
                wv[b] = (gg < M) ? weights[gg] : OOR_VAL;
            }
        }
        #pragma unroll
        for (int k = 0; k < 16; ++k) {
            unsigned lo = __float_as_uint(-wv[2*k]);
            unsigned hi = __float_as_uint(-wv[2*k+1]);
            nwp[k] = ((unsigned long long)hi << 32) | lo;
        }
    }
    // per-lane halo weights for the warp's segment edges
    float hwl, hwr;
    {
        int gl = segbase - 32 + lane;          // cols [segbase-32, segbase)
        int gr = segbase + SEG + lane;         // cols [segbase+SEG, segbase+SEG+32)
        hwl = (gl >= 0 && gl < M) ? __ldg(weights + gl) : OOR_VAL;
        hwr = (gr < M)            ? __ldg(weights + gr) : OOR_VAL;
    }

    const unsigned long long c2 =
        ((unsigned long long)__float_as_uint(-0.01f) << 32) | __float_as_uint(-0.01f);

    const int row0 = blockIdx.y * ROWS_PER_BLOCK;
    const int shamt = (lane & 7) * 4;
    const int srcbase = lane >> 3;

    #pragma unroll 1
    for (int r = 0; r < ROWS_PER_BLOCK; ++r) {
        int i = row0 + r;
        if (i >= N) i = N - 1;
        const float vi = __ldg(&in_feat[i]);

        // ---- mask word + halo words (warp-local, no smem, no block sync) ----
        const unsigned long long vv =
            ((unsigned long long)__float_as_uint(vi) << 32) | __float_as_uint(vi);
        const unsigned m = mask32_sq(vv, nwp, c2);
        const unsigned hl = __ballot_sync(0xFFFFFFFFu, fabsf(vi - hwl) < THRESH);
        const unsigned hr = __ballot_sync(0xFFFFFFFFu, fabsf(vi - hwr) < THRESH);

        unsigned wm1 = __shfl_up_sync(0xFFFFFFFFu, m, 1);
        unsigned wp1 = __shfl_down_sync(0xFFFFFFFFu, m, 1);
        if (lane == 0)  wm1 = hl;
        if (lane == 31) wp1 = hr;

        // ---- width-51 sliding OR (radius 25) via log-step dilation ----
        unsigned long long lo = (unsigned long long)wm1 | ((unsigned long long)m << 32);
        unsigned long long hi = (unsigned long long)m   | ((unsigned long long)wp1 << 32);
        hi |= hi >> 1;  hi |= hi >> 2;  hi |= hi >> 4;  hi |= hi >> 8;  hi |= hi >> 10;
        lo |= lo << 1;  lo |= lo << 2;  lo |= lo << 4;  lo |= lo << 8;  lo |= lo << 10;
        const unsigned p = (unsigned)hi | (unsigned)(lo >> 32);

        // ---- coalesced emit: warp covers its 1024 contiguous columns ----
        float* wout = out + (size_t)i * (size_t)M + segbase;
        #pragma unroll
        for (int s = 0; s < 8; ++s) {
            unsigned src = __shfl_sync(0xFFFFFFFFu, p, s * 4 + srcbase);
            unsigned bits = src >> shamt;
            float4 v;
            v.x = __uint_as_float((bits & 1u) * 0x3F800000u);
            v.y = __uint_as_float((bits & 2u) * 0x1FC00000u);
            v.z = __uint_as_float((bits & 4u) * 0x0FE00000u);
            v.w = __uint_as_float((bits & 8u) * 0x07F00000u);
            __stcs(reinterpret_cast<float4*>(wout + s * 128) + lane, v);
        }
    }
}

extern "C" void kernel_launch(void* const* d_in, const int* in_sizes, int n_in,
                              void* d_out, int out_size)
{
    const float* in_feat = (const float*)d_in[0];   // 1024 elements
    const float* weights = (const float*)d_in[1];   // 262144 elements
    float* out = (float*)d_out;

    const int N = in_sizes[0];
    const int M = in_sizes[1];

    dim3 grid((M + CHUNK - 1) / CHUNK, (N + ROWS_PER_BLOCK - 1) / ROWS_PER_BLOCK);
    cll_pool_kernel<<<grid, THREADS>>>(in_feat, weights, out, N, M);
}